// round 13
// baseline (speedup 1.0000x reference)
#include <cuda_runtime.h>
#include <cuda_bf16.h>
#include <cstdint>

// Inputs (metadata order):
//   d_in[0] = x      float32 [262144]  (1 MB, random-gathered, L2-resident)
//   d_in[1] = A_vals float32 [NNZ]     (streamed once)
//   d_in[2] = A_rows int32   [NNZ]     (streamed once)
//   d_in[3] = A_cols int32   [NNZ]     (streamed once)
// Output: float32 [262144]
//
// Unsorted-COO SpMV at the co-saturated L1tex/LTS floor. Geometry gradient:
// 256thr/8192CTA = 66-67us, 512thr/4096CTA = 65.3us (best). R13 probes
// 1024thr/2048CTA. Everything else identical to the best configuration.

#define THREADS 1024

__global__ void zero_out_kernel(float4* __restrict__ out, int n4) {
    int i = blockIdx.x * blockDim.x + threadIdx.x;
    if (i < n4) out[i] = make_float4(0.f, 0.f, 0.f, 0.f);
}

__global__ void __launch_bounds__(THREADS) coo_spmv_kernel(
    const float*  __restrict__ x,
    const float4* __restrict__ vals4,
    const int4*   __restrict__ rows4,
    const int4*   __restrict__ cols4,
    float*        __restrict__ out,
    int nnz4)
{
    int i = blockIdx.x * blockDim.x + threadIdx.x;
    if (i >= nnz4) return;

    // Three independent 16B streaming loads -> MLP 3 per thread.
    float4 v = __ldg(&vals4[i]);
    int4   r = __ldg(&rows4[i]);
    int4   c = __ldg(&cols4[i]);

    // Random gathers from L2-resident x (1 MB).
    float x0 = __ldg(&x[c.x]);
    float x1 = __ldg(&x[c.y]);
    float x2 = __ldg(&x[c.z]);
    float x3 = __ldg(&x[c.w]);

    // Scatter-add: return value unused -> RED.E.ADD.F32 at L2.
    atomicAdd(&out[r.x], v.x * x0);
    atomicAdd(&out[r.y], v.y * x1);
    atomicAdd(&out[r.z], v.z * x2);
    atomicAdd(&out[r.w], v.w * x3);
}

// Tail handler for nnz not divisible by 4 (host-guarded out for this shape).
__global__ void coo_spmv_tail_kernel(
    const float* __restrict__ x,
    const float* __restrict__ vals,
    const int*   __restrict__ rows,
    const int*   __restrict__ cols,
    float*       __restrict__ out,
    int start, int nnz)
{
    int i = start + blockIdx.x * blockDim.x + threadIdx.x;
    if (i < nnz) {
        atomicAdd(&out[rows[i]], vals[i] * __ldg(&x[cols[i]]));
    }
}

extern "C" void kernel_launch(void* const* d_in, const int* in_sizes, int n_in,
                              void* d_out, int out_size) {
    const float* x    = (const float*)d_in[0];
    const float* vals = (const float*)d_in[1];
    const int*   rows = (const int*)d_in[2];
    const int*   cols = (const int*)d_in[3];
    float* out = (float*)d_out;

    const int nnz = in_sizes[1];

    // Zero-init output (harness poisons it to 0xAA).
    {
        int n4 = out_size / 4;               // out_size divisible by 4 here
        zero_out_kernel<<<(n4 + 255) / 256, 256>>>((float4*)out, n4);
    }

    // Main vectorized COO pass: 4 nnz per thread, 1024-thread blocks.
    int nnz4 = nnz / 4;
    if (nnz4 > 0) {
        int blocks = (nnz4 + THREADS - 1) / THREADS;   // 2048 for this shape
        coo_spmv_kernel<<<blocks, THREADS>>>(
            x, (const float4*)vals, (const int4*)rows, (const int4*)cols, out, nnz4);
    }

    // Tail (nnz % 4): empty for this shape -> no node enters the graph.
    int tail_start = nnz4 * 4;
    int tail = nnz - tail_start;
    if (tail > 0) {
        coo_spmv_tail_kernel<<<(tail + 255) / 256, 256>>>(
            x, vals, rows, cols, out, tail_start, nnz);
    }
}

// round 14
// speedup vs baseline: 1.0009x; 1.0009x over previous
#include <cuda_runtime.h>
#include <cuda_bf16.h>
#include <cstdint>

// Inputs (metadata order):
//   d_in[0] = x      float32 [262144]  (1 MB, random-gathered, L2-resident)
//   d_in[1] = A_vals float32 [NNZ]     (streamed once)
//   d_in[2] = A_rows int32   [NNZ]     (streamed once)
//   d_in[3] = A_cols int32   [NNZ]     (streamed once)
// Output: float32 [262144]
//
// Unsorted-COO SpMV at the co-saturated L1tex/LTS floor (~65.3us kernel).
// Geometry optimum measured: 512thr/4096CTA (256->66.9, 512->65.3, 1024->67.2).
// Init optimum measured: cudaMemsetAsync node (~3.4us gap vs ~4.3us for a
// zero kernel). R14 = best kernel (R12) + best init (R2/R6), first pairing.

#define THREADS 512

__global__ void __launch_bounds__(THREADS) coo_spmv_kernel(
    const float*  __restrict__ x,
    const float4* __restrict__ vals4,
    const int4*   __restrict__ rows4,
    const int4*   __restrict__ cols4,
    float*        __restrict__ out,
    int nnz4)
{
    int i = blockIdx.x * blockDim.x + threadIdx.x;
    if (i >= nnz4) return;

    // Three independent 16B streaming loads -> MLP 3 per thread.
    float4 v = __ldg(&vals4[i]);
    int4   r = __ldg(&rows4[i]);
    int4   c = __ldg(&cols4[i]);

    // Random gathers from L2-resident x (1 MB).
    float x0 = __ldg(&x[c.x]);
    float x1 = __ldg(&x[c.y]);
    float x2 = __ldg(&x[c.z]);
    float x3 = __ldg(&x[c.w]);

    // Scatter-add: return value unused -> RED.E.ADD.F32 at L2.
    atomicAdd(&out[r.x], v.x * x0);
    atomicAdd(&out[r.y], v.y * x1);
    atomicAdd(&out[r.z], v.z * x2);
    atomicAdd(&out[r.w], v.w * x3);
}

// Tail handler for nnz not divisible by 4 (host-guarded out for this shape).
__global__ void coo_spmv_tail_kernel(
    const float* __restrict__ x,
    const float* __restrict__ vals,
    const int*   __restrict__ rows,
    const int*   __restrict__ cols,
    float*       __restrict__ out,
    int start, int nnz)
{
    int i = start + blockIdx.x * blockDim.x + threadIdx.x;
    if (i < nnz) {
        atomicAdd(&out[rows[i]], vals[i] * __ldg(&x[cols[i]]));
    }
}

extern "C" void kernel_launch(void* const* d_in, const int* in_sizes, int n_in,
                              void* d_out, int out_size) {
    const float* x    = (const float*)d_in[0];
    const float* vals = (const float*)d_in[1];
    const int*   rows = (const int*)d_in[2];
    const int*   cols = (const int*)d_in[3];
    float* out = (float*)d_out;

    const int nnz = in_sizes[1];

    // Zero-init output (harness poisons it to 0xAA). Memset node: cheapest
    // measured init (~0.8-1.0us under a zero kernel).
    cudaMemsetAsync(out, 0, (size_t)out_size * sizeof(float), 0);

    // Main vectorized COO pass: 4 nnz per thread, 512-thread blocks (optimum).
    int nnz4 = nnz / 4;
    if (nnz4 > 0) {
        int blocks = (nnz4 + THREADS - 1) / THREADS;   // 4096 for this shape
        coo_spmv_kernel<<<blocks, THREADS>>>(
            x, (const float4*)vals, (const int4*)rows, (const int4*)cols, out, nnz4);
    }

    // Tail (nnz % 4): empty for this shape -> no node enters the graph.
    int tail_start = nnz4 * 4;
    int tail = nnz - tail_start;
    if (tail > 0) {
        coo_spmv_tail_kernel<<<(tail + 255) / 256, 256>>>(
            x, vals, rows, cols, out, tail_start, nnz);
    }
}